// round 1
// baseline (speedup 1.0000x reference)
#include <cuda_runtime.h>
#include <cuda_bf16.h>
#include <math.h>

// Problem constants
#define E_DIM 768
#define H_NUM 12
#define D_DIM 64
#define B_NUM 4
#define S_LEN 2048
#define M_ROWS (B_NUM * S_LEN)   // 8192

// Scratch (static device globals: allocation-free)
__device__ float g_Qh[B_NUM * H_NUM * S_LEN * D_DIM];   // [B,H,S,D]
__device__ float g_Kh[B_NUM * H_NUM * S_LEN * D_DIM];
__device__ float g_Vh[B_NUM * H_NUM * S_LEN * D_DIM];
__device__ float g_ctx[M_ROWS * E_DIM];                 // [B,S,E]

// ---------------------------------------------------------------------------
// Tiled SGEMM: C[64x64] per block, BK=16, 256 threads, 4x4 microtile/thread.
// X: [M,768] row-major.  W: [768,768] row-major.  bias: [768].
// HEADS_OUT: write out[((b*H+h)*S+s)*64+d] instead of out[m*768+n].
// ---------------------------------------------------------------------------
template <bool HEADS_OUT>
__global__ __launch_bounds__(256) void gemm64(const float* __restrict__ X,
                                              const float* __restrict__ W,
                                              const float* __restrict__ bias,
                                              float* __restrict__ out) {
    __shared__ float As[16][64];   // [k][m]
    __shared__ float Bs[16][64];   // [k][n]

    const int tid = threadIdx.x;
    const int tx = tid & 15;
    const int ty = tid >> 4;
    const int m0 = blockIdx.y * 64;
    const int n0 = blockIdx.x * 64;

    const int lm = tid >> 2;          // 0..63  (A row)
    const int lq = (tid & 3) * 4;     // 0,4,8,12 (A k-quad)
    const int lk = tid >> 4;          // 0..15  (B k)
    const int ln = (tid & 15) * 4;    // B n-quad

    float acc[4][4];
#pragma unroll
    for (int i = 0; i < 4; i++)
#pragma unroll
        for (int j = 0; j < 4; j++) acc[i][j] = 0.0f;

    for (int k0 = 0; k0 < E_DIM; k0 += 16) {
        float4 a = *(const float4*)&X[(m0 + lm) * E_DIM + k0 + lq];
        As[lq + 0][lm] = a.x;
        As[lq + 1][lm] = a.y;
        As[lq + 2][lm] = a.z;
        As[lq + 3][lm] = a.w;
        *(float4*)&Bs[lk][ln] = *(const float4*)&W[(k0 + lk) * E_DIM + n0 + ln];
        __syncthreads();

#pragma unroll
        for (int kk = 0; kk < 16; kk++) {
            float4 a4 = *(const float4*)&As[kk][ty * 4];
            float4 b4 = *(const float4*)&Bs[kk][tx * 4];
            float av[4] = {a4.x, a4.y, a4.z, a4.w};
            float bv[4] = {b4.x, b4.y, b4.z, b4.w};
#pragma unroll
            for (int i = 0; i < 4; i++)
#pragma unroll
                for (int j = 0; j < 4; j++) acc[i][j] = fmaf(av[i], bv[j], acc[i][j]);
        }
        __syncthreads();
    }

#pragma unroll
    for (int i = 0; i < 4; i++) {
        const int m = m0 + ty * 4 + i;
#pragma unroll
        for (int j = 0; j < 4; j++) {
            const int n = n0 + tx * 4 + j;
            const float v = acc[i][j] + bias[n];
            if (HEADS_OUT) {
                const int b = m / S_LEN, s = m % S_LEN;
                const int h = n >> 6, d = n & 63;
                out[((b * H_NUM + h) * S_LEN + s) * D_DIM + d] = v;
            } else {
                out[m * E_DIM + n] = v;
            }
        }
    }
}

// ---------------------------------------------------------------------------
// Flash attention: one block per (q-tile of 64, head, batch). 256 threads.
// Online softmax with key padding mask. D=64.
// smem: Qs[64][65], KsT[64][64] ([d][key]), Vs[64][64], Ps[64][64], bias[64]
// ---------------------------------------------------------------------------
__global__ __launch_bounds__(256) void attn64(const int* __restrict__ mask,
                                              const float* __restrict__ Qh,
                                              const float* __restrict__ Kh,
                                              const float* __restrict__ Vh,
                                              float* __restrict__ ctx) {
    extern __shared__ float sm[];
    float* Qs = sm;                  // 64*65
    float* KsT = Qs + 64 * 65;       // 64*64, [d][key]
    float* Vs = KsT + 64 * 64;       // 64*64, [key][d]
    float* Ps = Vs + 64 * 64;        // 64*64, [q][key]
    float* biasS = Ps + 64 * 64;     // 64

    const int b = blockIdx.z;
    const int h = blockIdx.y;
    const int q0 = blockIdx.x * 64;

    const int tid = threadIdx.x;
    const int tx = tid & 15;
    const int ty = tid >> 4;
    const int lr = tid >> 2;         // 0..63
    const int lq4 = (tid & 3) * 4;   // 0,4,8,12

    const long base = ((long)(b * H_NUM + h)) * S_LEN * D_DIM;
    const float* Q = Qh + base;
    const float* K = Kh + base;
    const float* V = Vh + base;

    // Load Q tile into shared (padded stride 65)
#pragma unroll
    for (int c4 = 0; c4 < 4; c4++) {
        const int col = lq4 + c4 * 16;
        float4 qv = *(const float4*)&Q[(q0 + lr) * D_DIM + col];
        Qs[lr * 65 + col + 0] = qv.x;
        Qs[lr * 65 + col + 1] = qv.y;
        Qs[lr * 65 + col + 2] = qv.z;
        Qs[lr * 65 + col + 3] = qv.w;
    }

    float m_i[4], l_i[4], o[4][4];
#pragma unroll
    for (int i = 0; i < 4; i++) {
        m_i[i] = -INFINITY;
        l_i[i] = 0.0f;
#pragma unroll
        for (int j = 0; j < 4; j++) o[i][j] = 0.0f;
    }

    const float scale = 0.125f;  // 1/sqrt(64)

    for (int k0 = 0; k0 < S_LEN; k0 += 64) {
        __syncthreads();  // prev-iter PV reads done; Q loaded (iter 0)

        // K tile -> KsT transposed; V tile -> Vs; mask bias
#pragma unroll
        for (int c4 = 0; c4 < 4; c4++) {
            const int col = lq4 + c4 * 16;
            float4 kv = *(const float4*)&K[(k0 + lr) * D_DIM + col];
            KsT[(col + 0) * 64 + lr] = kv.x;
            KsT[(col + 1) * 64 + lr] = kv.y;
            KsT[(col + 2) * 64 + lr] = kv.z;
            KsT[(col + 3) * 64 + lr] = kv.w;
            *(float4*)&Vs[lr * 64 + col] = *(const float4*)&V[(k0 + lr) * D_DIM + col];
        }
        if (tid < 64) biasS[tid] = (mask[b * S_LEN + k0 + tid] == 0) ? -1e9f : 0.0f;
        __syncthreads();

        // S = Q K^T tile (64x64), 4x4 per thread
        float s[4][4];
#pragma unroll
        for (int i = 0; i < 4; i++)
#pragma unroll
            for (int j = 0; j < 4; j++) s[i][j] = 0.0f;

#pragma unroll 8
        for (int d = 0; d < 64; d++) {
            float4 kb = *(const float4*)&KsT[d * 64 + tx * 4];
            float kv[4] = {kb.x, kb.y, kb.z, kb.w};
#pragma unroll
            for (int i = 0; i < 4; i++) {
                const float qa = Qs[(ty * 4 + i) * 65 + d];
#pragma unroll
                for (int j = 0; j < 4; j++) s[i][j] = fmaf(qa, kv[j], s[i][j]);
            }
        }

        // scale + mask bias
        float bcol[4];
#pragma unroll
        for (int j = 0; j < 4; j++) bcol[j] = biasS[tx * 4 + j];
#pragma unroll
        for (int i = 0; i < 4; i++)
#pragma unroll
            for (int j = 0; j < 4; j++) s[i][j] = s[i][j] * scale + bcol[j];

        // online softmax update
        float alpha[4];
#pragma unroll
        for (int i = 0; i < 4; i++) {
            float mt = fmaxf(fmaxf(s[i][0], s[i][1]), fmaxf(s[i][2], s[i][3]));
#pragma unroll
            for (int off = 8; off >= 1; off >>= 1)
                mt = fmaxf(mt, __shfl_xor_sync(0xffffffffu, mt, off));
            const float m_new = fmaxf(m_i[i], mt);
            alpha[i] = __expf(m_i[i] - m_new);
            float rs = 0.0f;
#pragma unroll
            for (int j = 0; j < 4; j++) {
                s[i][j] = __expf(s[i][j] - m_new);
                rs += s[i][j];
            }
#pragma unroll
            for (int off = 8; off >= 1; off >>= 1)
                rs += __shfl_xor_sync(0xffffffffu, rs, off);
            l_i[i] = l_i[i] * alpha[i] + rs;
            m_i[i] = m_new;
#pragma unroll
            for (int j = 0; j < 4; j++) o[i][j] *= alpha[i];
        }

        // write P, then PV
#pragma unroll
        for (int i = 0; i < 4; i++)
            *(float4*)&Ps[(ty * 4 + i) * 64 + tx * 4] =
                make_float4(s[i][0], s[i][1], s[i][2], s[i][3]);
        __syncthreads();

#pragma unroll 8
        for (int k = 0; k < 64; k++) {
            float4 vb = *(const float4*)&Vs[k * 64 + tx * 4];
            float vv[4] = {vb.x, vb.y, vb.z, vb.w};
#pragma unroll
            for (int i = 0; i < 4; i++) {
                const float p = Ps[(ty * 4 + i) * 64 + k];
#pragma unroll
                for (int j = 0; j < 4; j++) o[i][j] = fmaf(p, vv[j], o[i][j]);
            }
        }
    }

    // epilogue: ctx[b][q0+r][h*64 + c] = o / l
#pragma unroll
    for (int i = 0; i < 4; i++) {
        const float inv_l = 1.0f / l_i[i];
        const int s_idx = q0 + ty * 4 + i;
        float* dst = ctx + ((long)b * S_LEN + s_idx) * E_DIM + h * D_DIM + tx * 4;
        dst[0] = o[i][0] * inv_l;
        dst[1] = o[i][1] * inv_l;
        dst[2] = o[i][2] * inv_l;
        dst[3] = o[i][3] * inv_l;
    }
}

// ---------------------------------------------------------------------------
extern "C" void kernel_launch(void* const* d_in, const int* in_sizes, int n_in,
                              void* d_out, int out_size) {
    const float* q = (const float*)d_in[0];
    const float* k = (const float*)d_in[1];
    const float* v = (const float*)d_in[2];
    const int* mask = (const int*)d_in[3];
    const float* Wq = (const float*)d_in[4];
    const float* bq = (const float*)d_in[5];
    const float* Wk = (const float*)d_in[6];
    const float* bk = (const float*)d_in[7];
    const float* Wv = (const float*)d_in[8];
    const float* bv = (const float*)d_in[9];
    const float* Wo = (const float*)d_in[10];
    const float* bo = (const float*)d_in[11];

    float *Qh, *Kh, *Vh, *Ctx;
    cudaGetSymbolAddress((void**)&Qh, g_Qh);
    cudaGetSymbolAddress((void**)&Kh, g_Kh);
    cudaGetSymbolAddress((void**)&Vh, g_Vh);
    cudaGetSymbolAddress((void**)&Ctx, g_ctx);

    dim3 gemm_grid(E_DIM / 64, M_ROWS / 64);   // (12, 128)
    gemm64<true><<<gemm_grid, 256>>>(q, Wq, bq, Qh);
    gemm64<true><<<gemm_grid, 256>>>(k, Wk, bk, Kh);
    gemm64<true><<<gemm_grid, 256>>>(v, Wv, bv, Vh);

    const size_t smem = (size_t)(64 * 65 + 3 * 64 * 64 + 64) * sizeof(float);  // 66048 B
    cudaFuncSetAttribute(attn64, cudaFuncAttributeMaxDynamicSharedMemorySize, (int)smem);
    attn64<<<dim3(S_LEN / 64, H_NUM, B_NUM), 256, smem>>>(mask, Qh, Kh, Vh, Ctx);

    gemm64<false><<<gemm_grid, 256>>>(Ctx, Wo, bo, (float*)d_out);
}

// round 2
// speedup vs baseline: 2.7403x; 2.7403x over previous
#include <cuda_runtime.h>
#include <cuda_bf16.h>
#include <math.h>
#include <stdint.h>

#define E_DIM 768
#define H_NUM 12
#define D_DIM 64
#define B_NUM 4
#define S_LEN 2048
#define M_ROWS (B_NUM * S_LEN)   // 8192

// Scratch (static device globals: allocation-free)
__device__ float g_Qh[B_NUM * H_NUM * S_LEN * D_DIM];   // [B,H,S,D]
__device__ float g_Kh[B_NUM * H_NUM * S_LEN * D_DIM];
__device__ float g_Vh[B_NUM * H_NUM * S_LEN * D_DIM];
__device__ float g_ctx[M_ROWS * E_DIM];                 // [B,S,E]

// ---------------------------------------------------------------------------
// tf32 helpers
// ---------------------------------------------------------------------------
__device__ __forceinline__ uint32_t f2tf32(float x) {
    uint32_t u;
    asm("cvt.rna.tf32.f32 %0, %1;" : "=r"(u) : "f"(x));
    return u;
}

__device__ __forceinline__ void mma_tf32(float* d, const uint32_t* a,
                                         uint32_t b0, uint32_t b1) {
    asm volatile(
        "mma.sync.aligned.m16n8k8.row.col.f32.tf32.tf32.f32 "
        "{%0,%1,%2,%3}, {%4,%5,%6,%7}, {%8,%9}, {%0,%1,%2,%3};\n"
        : "+f"(d[0]), "+f"(d[1]), "+f"(d[2]), "+f"(d[3])
        : "r"(a[0]), "r"(a[1]), "r"(a[2]), "r"(a[3]), "r"(b0), "r"(b1));
}

__device__ __forceinline__ float ex2(float x) {
    float y;
    asm("ex2.approx.ftz.f32 %0, %1;" : "=f"(y) : "f"(x));
    return y;
}

// ---------------------------------------------------------------------------
// Tensor-core GEMM: C[M,768] = X[M,768] @ W[768,768] + bias.
// Block tile 128x64, BK=32, 256 threads (8 warps, 4x2 warp grid, 32x32/warp).
// HEADS_OUT: scatter into [B,H,S,D] layout.
// ---------------------------------------------------------------------------
template <bool HEADS_OUT>
__global__ __launch_bounds__(256) void gemm_tc(const float* __restrict__ X,
                                               const float* __restrict__ W,
                                               const float* __restrict__ bias,
                                               float* __restrict__ out) {
    __shared__ float As[128 * 36];  // [row][k] stride 36 (=4 mod 32)
    __shared__ float Bs[32 * 72];   // [k][n]   stride 72 (=8 mod 32)

    const int tid = threadIdx.x;
    const int w = tid >> 5, lane = tid & 31;
    const int wm = w >> 1, wn = w & 1;
    const int g = lane >> 2, c = lane & 3;
    const int m0 = blockIdx.y * 128, n0 = blockIdx.x * 64;

    float acc[2][4][4];
#pragma unroll
    for (int mt = 0; mt < 2; mt++)
#pragma unroll
        for (int nt = 0; nt < 4; nt++)
#pragma unroll
            for (int j = 0; j < 4; j++) acc[mt][nt][j] = 0.0f;

    for (int k0 = 0; k0 < E_DIM; k0 += 32) {
        // Load tiles
        {
            int r = tid >> 3;
            const int c4 = (tid & 7) * 4;
#pragma unroll
            for (int i = 0; i < 4; i++) {
                *(float4*)&As[r * 36 + c4] =
                    *(const float4*)&X[(m0 + r) * E_DIM + k0 + c4];
                r += 32;
            }
            int r2 = tid >> 4;
            const int cc = (tid & 15) * 4;
#pragma unroll
            for (int i = 0; i < 2; i++) {
                *(float4*)&Bs[r2 * 72 + cc] =
                    *(const float4*)&W[(k0 + r2) * E_DIM + n0 + cc];
                r2 += 16;
            }
        }
        __syncthreads();

#pragma unroll
        for (int ks = 0; ks < 4; ks++) {
            uint32_t a[2][4];
#pragma unroll
            for (int mt = 0; mt < 2; mt++) {
                const float* ap = &As[(wm * 32 + mt * 16 + g) * 36 + ks * 8 + c];
                a[mt][0] = f2tf32(ap[0]);
                a[mt][1] = f2tf32(ap[8 * 36]);
                a[mt][2] = f2tf32(ap[4]);
                a[mt][3] = f2tf32(ap[8 * 36 + 4]);
            }
#pragma unroll
            for (int nt = 0; nt < 4; nt++) {
                const uint32_t b0 =
                    f2tf32(Bs[(ks * 8 + c) * 72 + wn * 32 + nt * 8 + g]);
                const uint32_t b1 =
                    f2tf32(Bs[(ks * 8 + c + 4) * 72 + wn * 32 + nt * 8 + g]);
                mma_tf32(acc[0][nt], a[0], b0, b1);
                mma_tf32(acc[1][nt], a[1], b0, b1);
            }
        }
        __syncthreads();
    }

    // Epilogue
#pragma unroll
    for (int mt = 0; mt < 2; mt++) {
        const int r0 = m0 + wm * 32 + mt * 16 + g;
#pragma unroll
        for (int nt = 0; nt < 4; nt++) {
            const int col = n0 + wn * 32 + nt * 8 + 2 * c;
            const float bb0 = bias[col], bb1 = bias[col + 1];
            const float v00 = acc[mt][nt][0] + bb0;
            const float v01 = acc[mt][nt][1] + bb1;
            const float v10 = acc[mt][nt][2] + bb0;
            const float v11 = acc[mt][nt][3] + bb1;
            if (HEADS_OUT) {
                const int d = col & 63;  // head = blockIdx.x, d = col within 64
                const int b0i = r0 >> 11, s0 = r0 & 2047;
                const int r1 = r0 + 8;
                const int b1i = r1 >> 11, s1 = r1 & 2047;
                *(float2*)&out[((long)(b0i * H_NUM + blockIdx.x) * S_LEN + s0) * D_DIM + d] =
                    make_float2(v00, v01);
                *(float2*)&out[((long)(b1i * H_NUM + blockIdx.x) * S_LEN + s1) * D_DIM + d] =
                    make_float2(v10, v11);
            } else {
                *(float2*)&out[(long)r0 * E_DIM + col] = make_float2(v00, v01);
                *(float2*)&out[(long)(r0 + 8) * E_DIM + col] = make_float2(v10, v11);
            }
        }
    }
}

// ---------------------------------------------------------------------------
// Tensor-core flash attention. Block = 4 warps (128 thr), Br=64, Bc=64, D=64.
// Warp w owns q-rows [w*16, w*16+16) -> softmax stats stay inside a lane quad.
// Q kept in registers as pre-scaled tf32 fragments. Softmax in base-2.
// ---------------------------------------------------------------------------
#define SCALE2 (0.125f * 1.44269504088896f)  // 1/sqrt(64) * log2(e)

__global__ __launch_bounds__(128) void attn_tc(const int* __restrict__ mask,
                                               const float* __restrict__ Qh,
                                               const float* __restrict__ Kh,
                                               const float* __restrict__ Vh,
                                               float* __restrict__ ctx) {
    extern __shared__ float sm[];
    float* Ks = sm;                  // [64][68]  (stride 68 = 4 mod 32)
    float* Vs = Ks + 64 * 68;        // [64][72]  (stride 72 = 8 mod 32)
    float* Ps = Vs + 64 * 72;        // [64][68]
    float* biasS = Ps + 64 * 68;     // [64]

    const int b = blockIdx.z, h = blockIdx.y;
    const int q0 = blockIdx.x * 64;
    const int tid = threadIdx.x;
    const int w = tid >> 5, lane = tid & 31;
    const int g = lane >> 2, c = lane & 3;

    const long base = (long)(b * H_NUM + h) * S_LEN * D_DIM;
    const float* Q = Qh + base;
    const float* K = Kh + base;
    const float* V = Vh + base;

    // Q fragments (pre-scaled), held for the whole kernel: 32 regs
    uint32_t aq[8][4];
    {
        const float* q_r0 = Q + (long)(q0 + w * 16 + g) * D_DIM;
        const float* q_r1 = q_r0 + 8 * D_DIM;
#pragma unroll
        for (int ks = 0; ks < 8; ks++) {
            aq[ks][0] = f2tf32(q_r0[ks * 8 + c] * SCALE2);
            aq[ks][1] = f2tf32(q_r1[ks * 8 + c] * SCALE2);
            aq[ks][2] = f2tf32(q_r0[ks * 8 + c + 4] * SCALE2);
            aq[ks][3] = f2tf32(q_r1[ks * 8 + c + 4] * SCALE2);
        }
    }

    float O[8][4];
#pragma unroll
    for (int nt = 0; nt < 8; nt++)
#pragma unroll
        for (int j = 0; j < 4; j++) O[nt][j] = 0.0f;
    float mm0 = -1e30f, mm1 = -1e30f, l0 = 0.0f, l1 = 0.0f;

    for (int k0 = 0; k0 < S_LEN; k0 += 64) {
        __syncthreads();  // prev PV done before overwriting Ks/Vs
        {
            int r = tid >> 4;
            const int c4 = (tid & 15) * 4;
#pragma unroll
            for (int i = 0; i < 8; i++) {
                *(float4*)&Ks[r * 68 + c4] = *(const float4*)&K[(long)(k0 + r) * D_DIM + c4];
                *(float4*)&Vs[r * 72 + c4] = *(const float4*)&V[(long)(k0 + r) * D_DIM + c4];
                r += 8;
            }
            if (tid < 64)
                biasS[tid] = mask[b * S_LEN + k0 + tid] ? 0.0f : -1.442695e9f;
        }
        __syncthreads();

        // S = (Q*scale) K^T  (base-2 domain)
        float S[8][4];
#pragma unroll
        for (int nt = 0; nt < 8; nt++)
#pragma unroll
            for (int j = 0; j < 4; j++) S[nt][j] = 0.0f;

#pragma unroll
        for (int ks = 0; ks < 8; ks++) {
#pragma unroll
            for (int nt = 0; nt < 8; nt++) {
                const uint32_t b0 = f2tf32(Ks[(nt * 8 + g) * 68 + ks * 8 + c]);
                const uint32_t b1 = f2tf32(Ks[(nt * 8 + g) * 68 + ks * 8 + c + 4]);
                mma_tf32(S[nt], aq[ks], b0, b1);
            }
        }

        // mask bias + online softmax (rows r0 = w*16+g, r1 = r0+8)
        float mx0 = -1e30f, mx1 = -1e30f;
#pragma unroll
        for (int nt = 0; nt < 8; nt++) {
            const float bb0 = biasS[nt * 8 + 2 * c];
            const float bb1 = biasS[nt * 8 + 2 * c + 1];
            S[nt][0] += bb0;
            S[nt][1] += bb1;
            S[nt][2] += bb0;
            S[nt][3] += bb1;
            mx0 = fmaxf(mx0, fmaxf(S[nt][0], S[nt][1]));
            mx1 = fmaxf(mx1, fmaxf(S[nt][2], S[nt][3]));
        }
        mx0 = fmaxf(mx0, __shfl_xor_sync(0xffffffffu, mx0, 1));
        mx0 = fmaxf(mx0, __shfl_xor_sync(0xffffffffu, mx0, 2));
        mx1 = fmaxf(mx1, __shfl_xor_sync(0xffffffffu, mx1, 1));
        mx1 = fmaxf(mx1, __shfl_xor_sync(0xffffffffu, mx1, 2));

        const float M0 = fmaxf(mm0, mx0), M1 = fmaxf(mm1, mx1);
        const float a0 = ex2(mm0 - M0), a1 = ex2(mm1 - M1);
        mm0 = M0;
        mm1 = M1;

        float s0 = 0.0f, s1 = 0.0f;
#pragma unroll
        for (int nt = 0; nt < 8; nt++) {
            S[nt][0] = ex2(S[nt][0] - M0);
            S[nt][1] = ex2(S[nt][1] - M0);
            S[nt][2] = ex2(S[nt][2] - M1);
            S[nt][3] = ex2(S[nt][3] - M1);
            s0 += S[nt][0] + S[nt][1];
            s1 += S[nt][2] + S[nt][3];
        }
        s0 += __shfl_xor_sync(0xffffffffu, s0, 1);
        s0 += __shfl_xor_sync(0xffffffffu, s0, 2);
        s1 += __shfl_xor_sync(0xffffffffu, s1, 1);
        s1 += __shfl_xor_sync(0xffffffffu, s1, 2);
        l0 = l0 * a0 + s0;
        l1 = l1 * a1 + s1;

#pragma unroll
        for (int nt = 0; nt < 8; nt++) {
            O[nt][0] *= a0;
            O[nt][1] *= a0;
            O[nt][2] *= a1;
            O[nt][3] *= a1;
        }

        // write P tile
#pragma unroll
        for (int nt = 0; nt < 8; nt++) {
            const int col = nt * 8 + 2 * c;
            *(float2*)&Ps[(w * 16 + g) * 68 + col] = make_float2(S[nt][0], S[nt][1]);
            *(float2*)&Ps[(w * 16 + g + 8) * 68 + col] = make_float2(S[nt][2], S[nt][3]);
        }
        __syncthreads();

        // O += P @ V
#pragma unroll
        for (int ks = 0; ks < 8; ks++) {
            uint32_t ap[4];
            ap[0] = f2tf32(Ps[(w * 16 + g) * 68 + ks * 8 + c]);
            ap[1] = f2tf32(Ps[(w * 16 + g + 8) * 68 + ks * 8 + c]);
            ap[2] = f2tf32(Ps[(w * 16 + g) * 68 + ks * 8 + c + 4]);
            ap[3] = f2tf32(Ps[(w * 16 + g + 8) * 68 + ks * 8 + c + 4]);
#pragma unroll
            for (int nt = 0; nt < 8; nt++) {
                const uint32_t b0 = f2tf32(Vs[(ks * 8 + c) * 72 + nt * 8 + g]);
                const uint32_t b1 = f2tf32(Vs[(ks * 8 + c + 4) * 72 + nt * 8 + g]);
                mma_tf32(O[nt], ap, b0, b1);
            }
        }
    }

    // epilogue: ctx[b][row][h*64 + col] = O / l
    const float inv0 = 1.0f / l0, inv1 = 1.0f / l1;
    const int r0 = q0 + w * 16 + g;
#pragma unroll
    for (int nt = 0; nt < 8; nt++) {
        const int col = h * D_DIM + nt * 8 + 2 * c;
        *(float2*)&ctx[((long)b * S_LEN + r0) * E_DIM + col] =
            make_float2(O[nt][0] * inv0, O[nt][1] * inv0);
        *(float2*)&ctx[((long)b * S_LEN + r0 + 8) * E_DIM + col] =
            make_float2(O[nt][2] * inv1, O[nt][3] * inv1);
    }
}

// ---------------------------------------------------------------------------
extern "C" void kernel_launch(void* const* d_in, const int* in_sizes, int n_in,
                              void* d_out, int out_size) {
    const float* q = (const float*)d_in[0];
    const float* k = (const float*)d_in[1];
    const float* v = (const float*)d_in[2];
    const int* mask = (const int*)d_in[3];
    const float* Wq = (const float*)d_in[4];
    const float* bq = (const float*)d_in[5];
    const float* Wk = (const float*)d_in[6];
    const float* bk = (const float*)d_in[7];
    const float* Wv = (const float*)d_in[8];
    const float* bv = (const float*)d_in[9];
    const float* Wo = (const float*)d_in[10];
    const float* bo = (const float*)d_in[11];

    float *Qh, *Kh, *Vh, *Ctx;
    cudaGetSymbolAddress((void**)&Qh, g_Qh);
    cudaGetSymbolAddress((void**)&Kh, g_Kh);
    cudaGetSymbolAddress((void**)&Vh, g_Vh);
    cudaGetSymbolAddress((void**)&Ctx, g_ctx);

    dim3 ggrid(E_DIM / 64, M_ROWS / 128);  // (12, 64)
    gemm_tc<true><<<ggrid, 256>>>(q, Wq, bq, Qh);
    gemm_tc<true><<<ggrid, 256>>>(k, Wk, bk, Kh);
    gemm_tc<true><<<ggrid, 256>>>(v, Wv, bv, Vh);

    const size_t smem = (size_t)(64 * 68 + 64 * 72 + 64 * 68 + 64) * sizeof(float);
    cudaFuncSetAttribute(attn_tc, cudaFuncAttributeMaxDynamicSharedMemorySize, (int)smem);
    attn_tc<<<dim3(S_LEN / 64, H_NUM, B_NUM), 128, smem>>>(mask, Qh, Kh, Vh, Ctx);

    gemm_tc<false><<<ggrid, 256>>>(Ctx, Wo, bo, (float*)d_out);
}